// round 5
// baseline (speedup 1.0000x reference)
#include <cuda_runtime.h>
#include <math_constants.h>

// ---------------- configuration ---------------------------------------------
#define LOWB   20
#define NB1    4096             // top 12 bits of monotonic key
#define NB2    (1u << LOWB)     // low 20 bits: 1,048,576 bins
#define CHUNK  1024
#define NCHUNK (NB2 / CHUNK)

#define NBINS     128           // pass-1 value-space bins
#define WIN_LO    60            // speculative window: bins 60..67 == |x| < 1/32
#define WIN_HI    67
#define P1_THREADS 512
#define P1_WARPS   16
#define P1_BUFCAP  16384        // per-block speculative append buffer (u32)
#define P1_CNT_BYTES (P1_WARPS * NBINS * 32 * 2)          // 131072
#define P1_SMEM      (P1_CNT_BYTES + P1_BUFCAP * 4)       // 196608
#define FB_BUFCAP  16384
#define MAXN       33554432

// ---------------- device state (allocation-free) -----------------------------
__device__ unsigned g_hist1[NB1];
__device__ unsigned g_hist2[NB2];
__device__ unsigned g_part[NCHUNK];
__device__ unsigned g_bins[NBINS];
__device__ unsigned g_scratch[MAXN];       // compacted candidate keys
__device__ unsigned g_m;                   // #keys in g_scratch
__device__ unsigned g_overflow;
__device__ unsigned g_use_fallback;
__device__ unsigned g_bsel;
__device__ unsigned g_scratch_rank;        // rank of median within g_scratch
__device__ unsigned g_b1, g_k2, g_chunk, g_k3;
__device__ float    g_median;

// monotonic key: order-preserving float -> uint
__device__ __forceinline__ unsigned fkey(float f) {
    unsigned b = __float_as_uint(f);
    unsigned mask = (unsigned)((int)b >> 31) | 0x80000000u;
    return b ^ mask;
}

__device__ __forceinline__ int vbin(float f) {
    int b = __float2int_rd(f * 128.0f) + 64;
    b = b < 0 ? 0 : b;
    b = b > (NBINS - 1) ? (NBINS - 1) : b;
    return b;
}

// ---------------- zero state -------------------------------------------------
__global__ void zero_kernel() {
    unsigned i = blockIdx.x * blockDim.x + threadIdx.x;
    unsigned stride = gridDim.x * blockDim.x;
    for (unsigned j = i; j < NB2; j += stride) g_hist2[j] = 0;
    if (i < NB1)   g_hist1[i] = 0;
    if (i < NBINS) g_bins[i]  = 0;
    if (i == 0) { g_m = 0; g_overflow = 0; }
}

// ---------------- pass 1: atomic-free count + speculative compaction ---------
__global__ __launch_bounds__(P1_THREADS) void pass1_kernel(const float4* __restrict__ x, int n4) {
    extern __shared__ unsigned char sm[];
    unsigned short* cnt = (unsigned short*)sm;                 // [warp][bin][lane]
    unsigned* buf = (unsigned*)(sm + P1_CNT_BYTES);
    __shared__ unsigned s_cnt, s_base;

    int tid = threadIdx.x, warp = tid >> 5, lane = tid & 31;

    uint4* z = (uint4*)cnt;
    for (int i = tid; i < P1_CNT_BYTES / 16; i += P1_THREADS) z[i] = make_uint4(0, 0, 0, 0);
    if (tid == 0) s_cnt = 0;
    __syncthreads();

    unsigned short* my = cnt + warp * (NBINS * 32) + lane;

    auto proc = [&](float f) {
        int b = vbin(f);
        my[b * 32] = (unsigned short)(my[b * 32] + 1);         // per-lane: no atomics
        if ((unsigned)(b - WIN_LO) <= (unsigned)(WIN_HI - WIN_LO)) {
            unsigned p = atomicAdd(&s_cnt, 1u);                // rare (~2.5%)
            if (p < P1_BUFCAP) buf[p] = fkey(f);
            else g_overflow = 1u;
        }
    };

    int stride = gridDim.x * blockDim.x;
    int i = blockIdx.x * blockDim.x + tid;
    for (; i + 3 * stride < n4; i += 4 * stride) {             // MLP: 4 float4 in flight
        float4 v0 = x[i];
        float4 v1 = x[i + stride];
        float4 v2 = x[i + 2 * stride];
        float4 v3 = x[i + 3 * stride];
        proc(v0.x); proc(v0.y); proc(v0.z); proc(v0.w);
        proc(v1.x); proc(v1.y); proc(v1.z); proc(v1.w);
        proc(v2.x); proc(v2.y); proc(v2.z); proc(v2.w);
        proc(v3.x); proc(v3.y); proc(v3.z); proc(v3.w);
    }
    for (; i < n4; i += stride) {
        float4 v = x[i];
        proc(v.x); proc(v.y); proc(v.z); proc(v.w);
    }
    __syncthreads();

    // reduce per-lane counters -> g_bins (one warp per bin group, conflict-free)
    for (int b = warp; b < NBINS; b += P1_WARPS) {
        unsigned s = 0;
        #pragma unroll
        for (int w = 0; w < P1_WARPS; w++) s += cnt[w * (NBINS * 32) + b * 32 + lane];
        #pragma unroll
        for (int o = 16; o; o >>= 1) s += __shfl_down_sync(0xffffffffu, s, o);
        if (lane == 0) atomicAdd(&g_bins[b], s);
    }

    // flush speculative buffer to global scratch
    if (tid == 0) {
        unsigned c = s_cnt;
        if (c > P1_BUFCAP) { c = P1_BUFCAP; g_overflow = 1u; }
        s_cnt = c;
        s_base = atomicAdd(&g_m, c);
    }
    __syncthreads();
    for (unsigned j = tid; j < s_cnt; j += P1_THREADS) g_scratch[s_base + j] = buf[j];
}

// ---------------- pick the value-bin holding rank k; decide fallback ---------
__global__ void selbin_kernel(unsigned k) {
    if (threadIdx.x == 0) {
        unsigned cum = 0, cumw = 0, k2 = 0;
        int bsel = -1;
        for (int b = 0; b < NBINS; b++) {
            if (b == WIN_LO) cumw = cum;
            unsigned c = g_bins[b];
            if (bsel < 0 && k < cum + c) { bsel = b; k2 = k - cum; }
            cum += c;
        }
        g_bsel = (unsigned)bsel;
        bool hit = (bsel >= WIN_LO && bsel <= WIN_HI) && (g_overflow == 0u);
        g_use_fallback = hit ? 0u : 1u;
        g_scratch_rank = hit ? (k - cumw) : k2;
        if (!hit) g_m = 0;   // fallback re-fills scratch from 0
    }
}

// ---------------- fallback: exact compaction of the selected bin (gated) -----
__global__ __launch_bounds__(256) void fallback_kernel(const float4* __restrict__ x, int n4) {
    if (g_use_fallback == 0u) return;
    extern __shared__ unsigned fbuf[];
    __shared__ unsigned s_cnt, s_base;
    int tid = threadIdx.x;
    if (tid == 0) s_cnt = 0;
    __syncthreads();
    unsigned bsel = g_bsel;
    auto proc = [&](float f) {
        if ((unsigned)vbin(f) == bsel) {
            unsigned p = atomicAdd(&s_cnt, 1u);
            if (p < FB_BUFCAP) fbuf[p] = fkey(f);
        }
    };
    int stride = gridDim.x * blockDim.x;
    for (int i = blockIdx.x * blockDim.x + tid; i < n4; i += stride) {
        float4 v = x[i];
        proc(v.x); proc(v.y); proc(v.z); proc(v.w);
    }
    __syncthreads();
    if (tid == 0) s_base = atomicAdd(&g_m, s_cnt);
    __syncthreads();
    for (unsigned j = tid; j < s_cnt; j += 256) g_scratch[s_base + j] = fbuf[j];
}

// ---------------- selection over compacted keys ------------------------------
__global__ void hist1s_kernel() {
    __shared__ unsigned sh[NB1];
    for (int i = threadIdx.x; i < NB1; i += blockDim.x) sh[i] = 0;
    __syncthreads();
    unsigned m = g_m;
    unsigned stride = gridDim.x * blockDim.x;
    for (unsigned i = blockIdx.x * blockDim.x + threadIdx.x; i < m; i += stride)
        atomicAdd(&sh[g_scratch[i] >> LOWB], 1u);
    __syncthreads();
    for (int i = threadIdx.x; i < NB1; i += blockDim.x)
        if (sh[i]) atomicAdd(&g_hist1[i], sh[i]);
}

__global__ void select1_kernel() {
    __shared__ unsigned ps[1024];
    int t = threadIdx.x;
    unsigned k = g_scratch_rank;
    unsigned c0 = g_hist1[t * 4 + 0], c1 = g_hist1[t * 4 + 1];
    unsigned c2 = g_hist1[t * 4 + 2], c3 = g_hist1[t * 4 + 3];
    unsigned s = c0 + c1 + c2 + c3;
    ps[t] = s;
    __syncthreads();
    for (int off = 1; off < 1024; off <<= 1) {
        unsigned v = (t >= off) ? ps[t - off] : 0u;
        __syncthreads();
        ps[t] += v;
        __syncthreads();
    }
    unsigned incl = ps[t], excl = incl - s;
    if (k >= excl && k < incl) {
        unsigned r = k - excl, bin;
        if (r < c0)                { bin = t * 4 + 0; }
        else if (r < c0 + c1)      { bin = t * 4 + 1; r -= c0; }
        else if (r < c0 + c1 + c2) { bin = t * 4 + 2; r -= c0 + c1; }
        else                       { bin = t * 4 + 3; r -= c0 + c1 + c2; }
        g_b1 = bin;
        g_k2 = r;
    }
}

__global__ void hist2s_kernel() {
    unsigned b1 = g_b1;
    unsigned m = g_m;
    unsigned stride = gridDim.x * blockDim.x;
    for (unsigned i = blockIdx.x * blockDim.x + threadIdx.x; i < m; i += stride) {
        unsigned u = g_scratch[i];
        if ((u >> LOWB) == b1) atomicAdd(&g_hist2[u & (NB2 - 1u)], 1u);
    }
}

__global__ void part2_kernel() {
    __shared__ unsigned red[256];
    int b = blockIdx.x;
    unsigned s = 0;
    for (int i = threadIdx.x; i < CHUNK; i += 256) s += g_hist2[b * CHUNK + i];
    red[threadIdx.x] = s;
    __syncthreads();
    for (int off = 128; off > 0; off >>= 1) {
        if (threadIdx.x < off) red[threadIdx.x] += red[threadIdx.x + off];
        __syncthreads();
    }
    if (threadIdx.x == 0) g_part[b] = red[0];
}

__global__ void selchunk_kernel() {
    __shared__ unsigned ps[1024];
    int t = threadIdx.x;
    unsigned s = g_part[t];
    unsigned k = g_k2;
    ps[t] = s;
    __syncthreads();
    for (int off = 1; off < 1024; off <<= 1) {
        unsigned v = (t >= off) ? ps[t - off] : 0u;
        __syncthreads();
        ps[t] += v;
        __syncthreads();
    }
    unsigned incl = ps[t], excl = incl - s;
    if (k >= excl && k < incl) { g_chunk = (unsigned)t; g_k3 = k - excl; }
}

__global__ void selfinal_kernel() {
    __shared__ unsigned ps[1024];
    int t = threadIdx.x;
    unsigned chunk = g_chunk;
    unsigned s = g_hist2[chunk * CHUNK + t];
    unsigned k = g_k3;
    ps[t] = s;
    __syncthreads();
    for (int off = 1; off < 1024; off <<= 1) {
        unsigned v = (t >= off) ? ps[t - off] : 0u;
        __syncthreads();
        ps[t] += v;
        __syncthreads();
    }
    unsigned incl = ps[t], excl = incl - s;
    if (k >= excl && k < incl) {
        unsigned key  = (g_b1 << LOWB) | (chunk * CHUNK + (unsigned)t);
        unsigned bits = (key & 0x80000000u) ? (key ^ 0x80000000u) : ~key;
        g_median = __uint_as_float(bits);
    }
}

// ---------------- fused threshold + 7x7 maxpool + local-max select -----------
#define TW 128
#define TH 32
#define HALO 3
#define SW (TW + 2 * HALO)   // 134
#define SH (TH + 2 * HALO)   // 38
#define IMG_W 2048
#define IMG_H 2048

__global__ __launch_bounds__(256) void nms_kernel(const float* __restrict__ x,
                                                  float* __restrict__ out) {
    __shared__ float sthr[SH][SW];
    __shared__ float shm[SH][TW];
    const float med = g_median;

    int tx = threadIdx.x & 31;
    int ty = threadIdx.x >> 5;
    int x0 = blockIdx.x * TW - HALO;
    int y0 = blockIdx.y * TH - HALO;
    const float* img = x + (size_t)blockIdx.z * IMG_W * IMG_H;
    float* oimg = out + (size_t)blockIdx.z * IMG_W * IMG_H;

    #pragma unroll
    for (int i = 0; i < 5; i++) {
        int r = ty + 8 * i;
        if (r < SH) {
            int gy = y0 + r;
            bool rowok = (gy >= 0 && gy < IMG_H);
            #pragma unroll
            for (int j = 0; j < 5; j++) {
                int c = tx + 32 * j;
                if (c < SW) {
                    int gx = x0 + c;
                    float v = -CUDART_INF_F;
                    if (rowok && gx >= 0 && gx < IMG_W) {
                        float t = img[(size_t)gy * IMG_W + gx];
                        v = (t > med) ? t : 0.0f;
                    }
                    sthr[r][c] = v;
                }
            }
        }
    }
    __syncthreads();

    #pragma unroll
    for (int i = 0; i < 5; i++) {
        int r = ty + 8 * i;
        if (r < SH) {
            #pragma unroll
            for (int j = 0; j < 4; j++) {
                int c = tx + 32 * j;
                float m = sthr[r][c];
                #pragma unroll
                for (int o = 1; o < 7; o++) m = fmaxf(m, sthr[r][c + o]);
                shm[r][c] = m;
            }
        }
    }
    __syncthreads();

    #pragma unroll
    for (int i = 0; i < 4; i++) {
        int r = ty + 8 * i;
        int gy = blockIdx.y * TH + r;
        #pragma unroll
        for (int j = 0; j < 4; j++) {
            int c = tx + 32 * j;
            float m = shm[r][c];
            #pragma unroll
            for (int o = 1; o < 7; o++) m = fmaxf(m, shm[r + o][c]);
            float v = sthr[r + HALO][c + HALO];
            int gx = blockIdx.x * TW + c;
            oimg[(size_t)gy * IMG_W + gx] = (v == m) ? v : 0.0f;
        }
    }
}

// ---------------- launch -----------------------------------------------------
extern "C" void kernel_launch(void* const* d_in, const int* in_sizes, int n_in,
                              void* d_out, int out_size) {
    const float* x = (const float*)d_in[0];
    float* out = (float*)d_out;
    int n = in_sizes[0];
    int n4 = n >> 2;
    unsigned k = (unsigned)((n - 1) / 2);

    int dev = 0, sms = 148;
    cudaGetDevice(&dev);
    cudaDeviceGetAttribute(&sms, cudaDevAttrMultiProcessorCount, dev);

    cudaFuncSetAttribute(pass1_kernel, cudaFuncAttributeMaxDynamicSharedMemorySize, P1_SMEM);
    cudaFuncSetAttribute(fallback_kernel, cudaFuncAttributeMaxDynamicSharedMemorySize, FB_BUFCAP * 4);

    zero_kernel<<<2048, 512>>>();
    pass1_kernel<<<sms, P1_THREADS, P1_SMEM>>>((const float4*)x, n4);
    selbin_kernel<<<1, 32>>>(k);
    fallback_kernel<<<2048, 256, FB_BUFCAP * 4>>>((const float4*)x, n4);
    hist1s_kernel<<<256, 256>>>();
    select1_kernel<<<1, 1024>>>();
    hist2s_kernel<<<256, 256>>>();
    part2_kernel<<<NCHUNK, 256>>>();
    selchunk_kernel<<<1, 1024>>>();
    selfinal_kernel<<<1, 1024>>>();
    nms_kernel<<<dim3(IMG_W / TW, IMG_H / TH, 8), 256>>>(x, out);
}

// round 6
// speedup vs baseline: 1.7581x; 1.7581x over previous
#include <cuda_runtime.h>
#include <math_constants.h>

// ---------------- configuration ---------------------------------------------
#define NB1    4096
#define NBB    1024
#define KEY_LO 0x42FFFFFFu   // fkey(-0.03125f)
#define KEY_HI 0xBD000000u   // fkey(+0.03125f)
#define P1_THREADS 512
#define P1_BUFCAP  8192
#define MAXN       33554432

// ---------------- device state (allocation-free) -----------------------------
__device__ __align__(16) unsigned g_scratch[MAXN];
__device__ unsigned g_hA[NB1];
__device__ unsigned g_hB[NBB];
__device__ unsigned g_hC[NBB];
__device__ unsigned g_below;
__device__ unsigned g_m;
__device__ unsigned g_overflow;
__device__ unsigned g_use_fallback;
__device__ unsigned g_scratch_rank;
__device__ unsigned g_b1, g_k2, g_b2, g_k3;
__device__ float    g_median;

// monotonic key: order-preserving float -> uint
__device__ __forceinline__ unsigned fkey(float f) {
    unsigned b = __float_as_uint(f);
    unsigned mask = (unsigned)((int)b >> 31) | 0x80000000u;
    return b ^ mask;
}

// ---------------- zero state (tiny) ------------------------------------------
__global__ void zero_kernel() {
    int t = threadIdx.x;
    #pragma unroll
    for (int j = 0; j < 4; j++) g_hA[t + 1024 * j] = 0;
    g_hB[t] = 0;
    g_hC[t] = 0;
    if (t == 0) { g_below = 0; g_m = 0; g_overflow = 0; }
}

// ---------------- pass 1: below-count + warp-aggregated window compaction ----
__global__ __launch_bounds__(P1_THREADS) void pass1_kernel(const float4* __restrict__ x,
                                                           int n4, int n) {
    __shared__ unsigned buf[P1_BUFCAP];
    __shared__ unsigned s_cnt, s_base;
    int tid = threadIdx.x, lane = tid & 31;
    if (tid == 0) s_cnt = 0;
    __syncthreads();

    unsigned below = 0;
    int stride = gridDim.x * blockDim.x;
    int i = blockIdx.x * blockDim.x + tid;
    const float4 FILL = make_float4(CUDART_INF_F, CUDART_INF_F, CUDART_INF_F, CUDART_INF_F);

    for (;;) {
        bool r0 = i < n4;
        if (!__any_sync(0xffffffffu, r0)) break;
        bool r1 = (i + stride) < n4;
        float4 v0 = FILL, v1 = FILL;          // +inf key: not below, not in window
        if (r0) v0 = x[i];
        if (r1) v1 = x[i + stride];

        unsigned kk[8];
        kk[0] = fkey(v0.x); kk[1] = fkey(v0.y); kk[2] = fkey(v0.z); kk[3] = fkey(v0.w);
        kk[4] = fkey(v1.x); kk[5] = fkey(v1.y); kk[6] = fkey(v1.z); kk[7] = fkey(v1.w);

        unsigned msk[8];
        unsigned tot = 0;
        #pragma unroll
        for (int j = 0; j < 8; j++) {
            below += (kk[j] < KEY_LO) ? 1u : 0u;
            bool w = (kk[j] >= KEY_LO) && (kk[j] < KEY_HI);
            msk[j] = __ballot_sync(0xffffffffu, w);
            tot += __popc(msk[j]);
        }
        if (tot) {
            unsigned base = 0;
            if (lane == 0) base = atomicAdd(&s_cnt, tot);
            base = __shfl_sync(0xffffffffu, base, 0);
            unsigned lanemask = (1u << lane) - 1u;
            #pragma unroll
            for (int j = 0; j < 8; j++) {
                if (msk[j] & (1u << lane)) {
                    unsigned p = base + __popc(msk[j] & lanemask);
                    if (p < P1_BUFCAP) buf[p] = kk[j];
                }
                base += __popc(msk[j]);
            }
        }
        i += 2 * stride;
    }

    // scalar tail (n not divisible by 4) — one thread, tiny
    if (blockIdx.x == 0 && tid == 0) {
        const float* xf = (const float*)x;
        for (int j = n4 * 4; j < n; j++) {
            unsigned key = fkey(xf[j]);
            if (key < KEY_LO) below++;
            else if (key < KEY_HI) { unsigned p = atomicAdd(&g_m, 1u); g_scratch[p] = key; }
        }
    }

    // reduce below-count: warp shuffle + one RED per warp
    #pragma unroll
    for (int o = 16; o; o >>= 1) below += __shfl_down_sync(0xffffffffu, below, o);
    if (lane == 0 && below) atomicAdd(&g_below, below);

    __syncthreads();
    if (tid == 0) {
        unsigned c = s_cnt;
        if (c > P1_BUFCAP) { c = P1_BUFCAP; g_overflow = 1u; }
        s_cnt = c;
        s_base = atomicAdd(&g_m, c);
    }
    __syncthreads();
    for (unsigned j = tid; j < s_cnt; j += P1_THREADS) g_scratch[s_base + j] = buf[j];
}

// ---------------- decide: speculation hit or fallback ------------------------
__global__ void decide_kernel(unsigned k, unsigned n) {
    if (threadIdx.x == 0) {
        unsigned below = g_below, m = g_m;
        bool hit = (g_overflow == 0u) && (k >= below) && ((k - below) < m);
        g_use_fallback = hit ? 0u : 1u;
        g_scratch_rank = hit ? (k - below) : k;
        if (!hit) g_m = n;     // fallback fills scratch[0..n) deterministically
    }
}

// ---------------- fallback: exact full compaction (gated, never hot) ---------
__global__ __launch_bounds__(256) void fallback_kernel(const float4* __restrict__ x,
                                                       int n4, int n) {
    if (g_use_fallback == 0u) return;
    int stride = gridDim.x * blockDim.x;
    uint4* s4 = (uint4*)g_scratch;
    for (int i = blockIdx.x * blockDim.x + threadIdx.x; i < n4; i += stride) {
        float4 v = x[i];
        s4[i] = make_uint4(fkey(v.x), fkey(v.y), fkey(v.z), fkey(v.w));
    }
    if (blockIdx.x == 0 && threadIdx.x == 0) {
        const float* xf = (const float*)x;
        for (int j = n4 * 4; j < n; j++) g_scratch[j] = fkey(xf[j]);
    }
}

// ---------------- selection: 12 + 10 + 10 bit refinement ---------------------
__global__ void histA_kernel() {
    __shared__ unsigned sh[NB1];
    for (int i = threadIdx.x; i < NB1; i += blockDim.x) sh[i] = 0;
    __syncthreads();
    unsigned m = g_m;
    unsigned stride = gridDim.x * blockDim.x;
    for (unsigned i = blockIdx.x * blockDim.x + threadIdx.x; i < m; i += stride)
        atomicAdd(&sh[g_scratch[i] >> 20], 1u);
    __syncthreads();
    for (int i = threadIdx.x; i < NB1; i += blockDim.x)
        if (sh[i]) atomicAdd(&g_hA[i], sh[i]);
}

__global__ void selA_kernel() {
    __shared__ unsigned ps[1024];
    int t = threadIdx.x;
    unsigned k = g_scratch_rank;
    unsigned c0 = g_hA[t * 4 + 0], c1 = g_hA[t * 4 + 1];
    unsigned c2 = g_hA[t * 4 + 2], c3 = g_hA[t * 4 + 3];
    unsigned s = c0 + c1 + c2 + c3;
    ps[t] = s;
    __syncthreads();
    for (int off = 1; off < 1024; off <<= 1) {
        unsigned v = (t >= off) ? ps[t - off] : 0u;
        __syncthreads();
        ps[t] += v;
        __syncthreads();
    }
    unsigned incl = ps[t], excl = incl - s;
    if (k >= excl && k < incl) {
        unsigned r = k - excl, bin;
        if (r < c0)                { bin = t * 4 + 0; }
        else if (r < c0 + c1)      { bin = t * 4 + 1; r -= c0; }
        else if (r < c0 + c1 + c2) { bin = t * 4 + 2; r -= c0 + c1; }
        else                       { bin = t * 4 + 3; r -= c0 + c1 + c2; }
        g_b1 = bin;
        g_k2 = r;
    }
}

__global__ void histB_kernel() {
    __shared__ unsigned sh[NBB];
    for (int i = threadIdx.x; i < NBB; i += blockDim.x) sh[i] = 0;
    __syncthreads();
    unsigned b1 = g_b1, m = g_m;
    unsigned stride = gridDim.x * blockDim.x;
    for (unsigned i = blockIdx.x * blockDim.x + threadIdx.x; i < m; i += stride) {
        unsigned u = g_scratch[i];
        if ((u >> 20) == b1) atomicAdd(&sh[(u >> 10) & 1023u], 1u);
    }
    __syncthreads();
    for (int i = threadIdx.x; i < NBB; i += blockDim.x)
        if (sh[i]) atomicAdd(&g_hB[i], sh[i]);
}

__global__ void histC_kernel() {
    __shared__ unsigned sh[NBB];
    for (int i = threadIdx.x; i < NBB; i += blockDim.x) sh[i] = 0;
    __syncthreads();
    unsigned hi = (g_b1 << 10) | g_b2;
    unsigned m = g_m;
    unsigned stride = gridDim.x * blockDim.x;
    for (unsigned i = blockIdx.x * blockDim.x + threadIdx.x; i < m; i += stride) {
        unsigned u = g_scratch[i];
        if ((u >> 10) == hi) atomicAdd(&sh[u & 1023u], 1u);
    }
    __syncthreads();
    for (int i = threadIdx.x; i < NBB; i += blockDim.x)
        if (sh[i]) atomicAdd(&g_hC[i], sh[i]);
}

// stage 0: pick b2 from g_hB; stage 1: pick final 10 bits from g_hC -> median
__global__ void selBC_kernel(int stage) {
    __shared__ unsigned ps[1024];
    int t = threadIdx.x;
    unsigned s = (stage == 0) ? g_hB[t] : g_hC[t];
    unsigned k = (stage == 0) ? g_k2 : g_k3;
    ps[t] = s;
    __syncthreads();
    for (int off = 1; off < 1024; off <<= 1) {
        unsigned v = (t >= off) ? ps[t - off] : 0u;
        __syncthreads();
        ps[t] += v;
        __syncthreads();
    }
    unsigned incl = ps[t], excl = incl - s;
    if (k >= excl && k < incl) {
        if (stage == 0) {
            g_b2 = (unsigned)t;
            g_k3 = k - excl;
        } else {
            unsigned key  = (g_b1 << 20) | (g_b2 << 10) | (unsigned)t;
            unsigned bits = (key & 0x80000000u) ? (key ^ 0x80000000u) : ~key;
            g_median = __uint_as_float(bits);
        }
    }
}

// ---------------- fused threshold + 7x7 maxpool + local-max select -----------
#define TW 128
#define TH 32
#define HALO 3
#define SW (TW + 2 * HALO)   // 134
#define SH (TH + 2 * HALO)   // 38
#define IMG_W 2048
#define IMG_H 2048

__global__ __launch_bounds__(256) void nms_kernel(const float* __restrict__ x,
                                                  float* __restrict__ out) {
    __shared__ float sthr[SH][SW];
    __shared__ float shm[SH][TW];
    const float med = g_median;

    int tx = threadIdx.x & 31;
    int ty = threadIdx.x >> 5;
    int x0 = blockIdx.x * TW - HALO;
    int y0 = blockIdx.y * TH - HALO;
    const float* img = x + (size_t)blockIdx.z * IMG_W * IMG_H;
    float* oimg = out + (size_t)blockIdx.z * IMG_W * IMG_H;

    #pragma unroll
    for (int i = 0; i < 5; i++) {
        int r = ty + 8 * i;
        if (r < SH) {
            int gy = y0 + r;
            bool rowok = (gy >= 0 && gy < IMG_H);
            #pragma unroll
            for (int j = 0; j < 5; j++) {
                int c = tx + 32 * j;
                if (c < SW) {
                    int gx = x0 + c;
                    float v = -CUDART_INF_F;
                    if (rowok && gx >= 0 && gx < IMG_W) {
                        float t = img[(size_t)gy * IMG_W + gx];
                        v = (t > med) ? t : 0.0f;
                    }
                    sthr[r][c] = v;
                }
            }
        }
    }
    __syncthreads();

    #pragma unroll
    for (int i = 0; i < 5; i++) {
        int r = ty + 8 * i;
        if (r < SH) {
            #pragma unroll
            for (int j = 0; j < 4; j++) {
                int c = tx + 32 * j;
                float m = sthr[r][c];
                #pragma unroll
                for (int o = 1; o < 7; o++) m = fmaxf(m, sthr[r][c + o]);
                shm[r][c] = m;
            }
        }
    }
    __syncthreads();

    #pragma unroll
    for (int i = 0; i < 4; i++) {
        int r = ty + 8 * i;
        int gy = blockIdx.y * TH + r;
        #pragma unroll
        for (int j = 0; j < 4; j++) {
            int c = tx + 32 * j;
            float m = shm[r][c];
            #pragma unroll
            for (int o = 1; o < 7; o++) m = fmaxf(m, shm[r + o][c]);
            float v = sthr[r + HALO][c + HALO];
            int gx = blockIdx.x * TW + c;
            oimg[(size_t)gy * IMG_W + gx] = (v == m) ? v : 0.0f;
        }
    }
}

// ---------------- launch -----------------------------------------------------
extern "C" void kernel_launch(void* const* d_in, const int* in_sizes, int n_in,
                              void* d_out, int out_size) {
    const float* x = (const float*)d_in[0];
    float* out = (float*)d_out;
    int n = in_sizes[0];
    int n4 = n >> 2;
    unsigned k = (unsigned)((n - 1) / 2);

    int dev = 0, sms = 148;
    cudaGetDevice(&dev);
    cudaDeviceGetAttribute(&sms, cudaDevAttrMultiProcessorCount, dev);

    zero_kernel<<<1, 1024>>>();
    pass1_kernel<<<sms * 4, P1_THREADS>>>((const float4*)x, n4, n);
    decide_kernel<<<1, 32>>>(k, (unsigned)n);
    fallback_kernel<<<sms * 8, 256>>>((const float4*)x, n4, n);
    histA_kernel<<<256, 256>>>();
    selA_kernel<<<1, 1024>>>();
    histB_kernel<<<256, 256>>>();
    selBC_kernel<<<1, 1024>>>(0);
    histC_kernel<<<256, 256>>>();
    selBC_kernel<<<1, 1024>>>(1);
    nms_kernel<<<dim3(IMG_W / TW, IMG_H / TH, 8), 256>>>(x, out);
}